// round 7
// baseline (speedup 1.0000x reference)
#include <cuda_runtime.h>
#include <math.h>
#include <cstdint>

#define L 8
#define E 8
#define R 64
#define H 2048
#define TOK 8192
#define SCALING 0.5f

#define TM 128
#define KSPLIT 8
#define KCH (H / KSPLIT)     // 256
#define BK 32
#define NC (KCH / BK)        // 8 chunks
#define XS 36                // aproj smem row stride (floats), 144B
#define HSS 68               // bproj smem row stride (floats)
#define NTILES (TOK / TM + E)   // 72 worst case

typedef unsigned long long ull;

#define FMA2(acc, a, b) asm("fma.rn.f32x2 %0, %1, %2, %0;" : "+l"(acc) : "l"(a), "l"(b))
#define CP16(d, s)  asm volatile("cp.async.cg.shared.global [%0], [%1], 16;" :: "r"(d), "l"(s))
#define CPCOMMIT()  asm volatile("cp.async.commit_group;" ::: "memory")
#define CPWAIT1()   asm volatile("cp.async.wait_group 1;" ::: "memory")

__device__ __forceinline__ uint32_t smem_u32(const void* p) {
    uint32_t a;
    asm("{.reg .u64 t; cvta.to.shared.u64 t, %1; cvt.u32.u64 %0, t;}" : "=r"(a) : "l"(p));
    return a;
}

// ---------------- scratch ----------------------------------------------------
__device__ float g_xmix[(size_t)TOK * H];
__device__ float g_hpart[KSPLIT][(size_t)TOK * R];
__device__ float g_h[(size_t)TOK * R];
__device__ float g_coef[TOK];
__device__ int   g_counts[E];
__device__ int   g_cnt[E];
__device__ int   g_tilestart[E + 1];
__device__ int   g_list[E * TOK];    // fixed per-expert regions

// ---------------- bookkeeping ------------------------------------------------
__global__ void reset_kernel() {
    if (threadIdx.x < E) g_counts[threadIdx.x] = 0;
}

__global__ void plan_kernel() {
    if (threadIdx.x == 0) {
        int ts = 0;
        for (int e = 0; e < E; e++) {
            int c = g_counts[e];
            g_cnt[e] = c;
            g_tilestart[e] = ts;
            g_counts[e] = 0;            // ready for next layer
            ts += (c + TM - 1) / TM;
        }
        g_tilestart[E] = ts;
    }
}

// ---------------- fused residual-mix + gating + scatter ----------------------
__global__ void __launch_bounds__(256) mix_gate_kernel(
    const float* __restrict__ xprev, const float* __restrict__ hx,
    const float* __restrict__ gw, const float* __restrict__ gates, int layer)
{
    int warp = threadIdx.x >> 5, lane = threadIdx.x & 31;
    int t = blockIdx.x * 8 + warp;

    float z = 1.0f / (1.0f + expf(-gates[layer]));
    float omz = 1.0f - z;

    const float* xp = xprev + (size_t)t * H;
    const float* hp = hx    + (size_t)t * H;
    float*       xm = g_xmix + (size_t)t * H;

    float acc[E];
#pragma unroll
    for (int e = 0; e < E; e++) acc[e] = 0.f;

#pragma unroll 4
    for (int j = 0; j < H / 128; j++) {
        int k = j * 128 + lane * 4;
        float4 a = *(const float4*)(xp + k);
        float4 b = *(const float4*)(hp + k);
        float4 v;
        v.x = z * a.x + omz * b.x;
        v.y = z * a.y + omz * b.y;
        v.z = z * a.z + omz * b.z;
        v.w = z * a.w + omz * b.w;
        *(float4*)(xm + k) = v;
#pragma unroll
        for (int e = 0; e < E; e++) {
            float4 w = *(const float4*)(gw + (size_t)e * H + k);
            acc[e] += v.x * w.x + v.y * w.y + v.z * w.z + v.w * w.w;
        }
    }
#pragma unroll
    for (int e = 0; e < E; e++)
#pragma unroll
        for (int o = 16; o > 0; o >>= 1)
            acc[e] += __shfl_xor_sync(0xffffffffu, acc[e], o);

    if (lane == 0) {
        float m = acc[0]; int g = 0;
#pragma unroll
        for (int e = 1; e < E; e++) if (acc[e] > m) { m = acc[e]; g = e; }
        float s = 0.f;
#pragma unroll
        for (int e = 0; e < E; e++) s += expf(acc[e] - m);
        g_coef[t] = SCALING / s;
        int pos = atomicAdd(&g_counts[g], 1);
        g_list[g * TOK + pos] = t;       // scatter fused (order irrelevant)
    }
}

// ---------------- A projection: cp.async 2-stage + LDS.128 FFMA2 GEMM --------
__global__ void __launch_bounds__(128) aproj_kernel(const float* __restrict__ A)
{
    extern __shared__ __align__(16) float dsm[];   // 2 stages x (128+64)*36 floats
    __shared__ int s_tok[TM];

    int gt = blockIdx.x;
    if (gt >= g_tilestart[E]) return;
    int part = blockIdx.y;
    int e = 0;
    while (gt >= g_tilestart[e + 1]) e++;
    int tile = gt - g_tilestart[e];
    int cnt  = g_cnt[e];

    int tid = threadIdx.x;
    int idx = tile * TM + tid;
    s_tok[tid] = (idx < cnt) ? g_list[e * TOK + idx] : -1;
    __syncthreads();

    int tok = s_tok[tid];
    int ctok = (tok >= 0) ? tok : s_tok[0];        // clamp: garbage rows masked at store
    const float* xsrc = g_xmix + (size_t)ctok * H + part * KCH;
    int ar = tid & 63, ahf = tid >> 6;
    const float* asrc = A + (size_t)e * R * H + (size_t)ar * H + part * KCH + ahf * 16;

    const int STG_F = (TM + R) * XS;               // floats per stage
    uint32_t sb = smem_u32(dsm);
    uint32_t xdst = sb + tid * XS * 4;
    uint32_t adst = sb + (TM * XS + ar * XS + ahf * 16) * 4;
    const uint32_t STGB = STG_F * 4;

#define STAGE(kb, soff) do {                                         \
        uint32_t xd = xdst + (soff);                                 \
        uint32_t ad = adst + (soff);                                 \
        _Pragma("unroll")                                            \
        for (int q = 0; q < 8; q++) CP16(xd + q * 16, xsrc + (kb) + q * 4); \
        _Pragma("unroll")                                            \
        for (int q = 0; q < 4; q++) CP16(ad + q * 16, asrc + (kb) + q * 4); \
        CPCOMMIT();                                                  \
    } while (0)

    STAGE(0, 0);

    int tm = tid >> 3, tn = tid & 7;
    ull acc[8][8];
#pragma unroll
    for (int i = 0; i < 8; i++)
#pragma unroll
        for (int j = 0; j < 8; j++) acc[i][j] = 0ULL;

    for (int kc = 0; kc < NC; kc++) {
        int nk = (kc + 1 < NC) ? (kc + 1) : (NC - 1);   // dead prefetch into unused buf
        STAGE(nk * BK, ((kc + 1) & 1) * STGB);
        CPWAIT1();
        __syncthreads();

        const ulonglong2* X2 = (const ulonglong2*)(dsm + (kc & 1) * STG_F);
        const ulonglong2* A2 = X2 + TM * XS / 4;
#pragma unroll 1
        for (int kq = 0; kq < BK / 4; kq++) {           // 4 k per iter via LDS.128
            ulonglong2 xv[8], bv[8];
#pragma unroll
            for (int i = 0; i < 8; i++) xv[i] = X2[(tm + 16 * i) * (XS / 4) + kq];
#pragma unroll
            for (int j = 0; j < 8; j++) bv[j] = A2[(tn + 8 * j) * (XS / 4) + kq];
#pragma unroll
            for (int i = 0; i < 8; i++)
#pragma unroll
                for (int j = 0; j < 8; j++) FMA2(acc[i][j], xv[i].x, bv[j].x);
#pragma unroll
            for (int i = 0; i < 8; i++)
#pragma unroll
                for (int j = 0; j < 8; j++) FMA2(acc[i][j], xv[i].y, bv[j].y);
        }
        __syncthreads();
    }
#undef STAGE

    float* hp = g_hpart[part];
#pragma unroll
    for (int i = 0; i < 8; i++) {
        int m = tm + 16 * i;
        int t2 = s_tok[m];
        if (t2 >= 0) {
#pragma unroll
            for (int j = 0; j < 8; j++) {
                ull a = acc[i][j];
                float lo = __uint_as_float((unsigned)a);
                float hi = __uint_as_float((unsigned)(a >> 32));
                hp[(size_t)t2 * R + tn + 8 * j] = lo + hi;
            }
        }
    }
}

// ---------------- reduce 8 K-partials (deterministic, tiny) -----------------
__global__ void hreduce_kernel() {
    int i = blockIdx.x * 256 + threadIdx.x;
    float4 s0, s1;
    {
        float4 a = ((const float4*)g_hpart[0])[i];
        float4 b = ((const float4*)g_hpart[1])[i];
        float4 c = ((const float4*)g_hpart[2])[i];
        float4 d = ((const float4*)g_hpart[3])[i];
        s0.x = (a.x + b.x) + (c.x + d.x);
        s0.y = (a.y + b.y) + (c.y + d.y);
        s0.z = (a.z + b.z) + (c.z + d.z);
        s0.w = (a.w + b.w) + (c.w + d.w);
    }
    {
        float4 a = ((const float4*)g_hpart[4])[i];
        float4 b = ((const float4*)g_hpart[5])[i];
        float4 c = ((const float4*)g_hpart[6])[i];
        float4 d = ((const float4*)g_hpart[7])[i];
        s1.x = (a.x + b.x) + (c.x + d.x);
        s1.y = (a.y + b.y) + (c.y + d.y);
        s1.z = (a.z + b.z) + (c.z + d.z);
        s1.w = (a.w + b.w) + (c.w + d.w);
    }
    float4 o;
    o.x = s0.x + s1.x; o.y = s0.y + s1.y; o.z = s0.z + s1.z; o.w = s0.w + s1.w;
    ((float4*)g_h)[i] = o;
}

// ---------------- B projection: LDS.128 FFMA2 GEMM ---------------------------
__global__ void __launch_bounds__(128) bproj_kernel(const float* __restrict__ Bm,
                                                    float* __restrict__ y)
{
    extern __shared__ __align__(16) float dsm[];
    float* Hs = dsm;                  // [TM][HSS]
    float* Bs = dsm + TM * HSS;       // [64][HSS]
    __shared__ int s_tok[TM];

    int gt = blockIdx.x;
    if (gt >= g_tilestart[E]) return;
    int e = 0;
    while (gt >= g_tilestart[e + 1]) e++;
    int tile = gt - g_tilestart[e];
    int cnt  = g_cnt[e];
    int h0   = blockIdx.y * 64;

    int tid = threadIdx.x;
    int idx = tile * TM + tid;
    s_tok[tid] = (idx < cnt) ? g_list[e * TOK + idx] : -1;
    __syncthreads();

    {
        int tok = s_tok[tid];
        int ct = (tok >= 0) ? tok : s_tok[0];
        const float4* hr = (const float4*)(g_h + (size_t)ct * R);
#pragma unroll
        for (int q = 0; q < 16; q++) *(float4*)&Hs[tid * HSS + q * 4] = hr[q];
        int r = tid & 63, hf = tid >> 6;
        const float* br = Bm + ((size_t)e * H + (size_t)(h0 + r)) * R + hf * 32;
#pragma unroll
        for (int q = 0; q < 8; q++)
            *(float4*)&Bs[r * HSS + hf * 32 + q * 4] = *(const float4*)(br + q * 4);
    }
    __syncthreads();

    int tm = tid >> 3, tn = tid & 7;
    const ulonglong2* H2 = (const ulonglong2*)Hs;
    const ulonglong2* B2 = (const ulonglong2*)Bs;

    ull acc[8][8];
#pragma unroll
    for (int i = 0; i < 8; i++)
#pragma unroll
        for (int j = 0; j < 8; j++) acc[i][j] = 0ULL;

#pragma unroll 1
    for (int kq = 0; kq < R / 4; kq++) {
        ulonglong2 xv[8], bv[8];
#pragma unroll
        for (int i = 0; i < 8; i++) xv[i] = H2[(tm + 16 * i) * (HSS / 4) + kq];
#pragma unroll
        for (int j = 0; j < 8; j++) bv[j] = B2[(tn + 8 * j) * (HSS / 4) + kq];
#pragma unroll
        for (int i = 0; i < 8; i++)
#pragma unroll
            for (int j = 0; j < 8; j++) FMA2(acc[i][j], xv[i].x, bv[j].x);
#pragma unroll
        for (int i = 0; i < 8; i++)
#pragma unroll
            for (int j = 0; j < 8; j++) FMA2(acc[i][j], xv[i].y, bv[j].y);
    }

#pragma unroll
    for (int i = 0; i < 8; i++) {
        int m = tm + 16 * i;
        int tok = s_tok[m];
        if (tok >= 0) {
            float c = __ldg(&g_coef[tok]);
            float* yr = y + (size_t)tok * H + h0;
#pragma unroll
            for (int j = 0; j < 8; j++) {
                ull a = acc[i][j];
                float lo = __uint_as_float((unsigned)a);
                float hi = __uint_as_float((unsigned)(a >> 32));
                yr[tn + 8 * j] = (lo + hi) * c;
            }
        }
    }
}

// ---------------- launcher ----------------------------------------------------
extern "C" void kernel_launch(void* const* d_in, const int* in_sizes, int n_in,
                              void* d_out, int out_size)
{
    const float* hs    = (const float*)d_in[0];  // [L+1, B, S, H]
    const float* gates = (const float*)d_in[1];  // [L]
    const float* A     = (const float*)d_in[2];  // [L, E, R, H]
    const float* Bm    = (const float*)d_in[3];  // [L, E, H, R]
    const float* gw    = (const float*)d_in[4];  // [L, E, H]
    float* y = (float*)d_out;

    const size_t HS = (size_t)TOK * H;
    const int ASM = 2 * (TM + R) * XS * 4;       // 55296 B
    const int BSM = (TM + 64) * HSS * 4;         // 52224 B

    cudaFuncSetAttribute(aproj_kernel, cudaFuncAttributeMaxDynamicSharedMemorySize, ASM);
    cudaFuncSetAttribute(bproj_kernel, cudaFuncAttributeMaxDynamicSharedMemorySize, BSM);

    reset_kernel<<<1, 32>>>();
    for (int i = 0; i < L; i++) {
        const float* xprev = (i == 0) ? hs : y;
        const float* hx    = hs + (size_t)((i == 0) ? 1 : i) * HS;

        mix_gate_kernel<<<TOK / 8, 256>>>(xprev, hx, gw + (size_t)i * E * H, gates, i);
        plan_kernel<<<1, 32>>>();
        aproj_kernel<<<dim3(NTILES, KSPLIT), 128, ASM>>>(A + (size_t)i * E * R * H);
        hreduce_kernel<<<TOK * R / 4 / 256, 256>>>();
        bproj_kernel<<<dim3(NTILES, H / 64), 128, BSM>>>(Bm + (size_t)i * E * H * R, y);
    }
}

// round 8
// speedup vs baseline: 1.4161x; 1.4161x over previous
#include <cuda_runtime.h>
#include <math.h>
#include <cstdint>

#define L 8
#define E 8
#define R 64
#define H 2048
#define TOK 8192
#define SCALING 0.5f

#define TM 128
#define KSPLIT 4
#define KCH (H / KSPLIT)     // 512
#define BK 32
#define NC (KCH / BK)        // 16
#define NTILES (TOK / TM + E)   // 72 worst case

// aproj smem layout (bytes, per stage): X rows stride 80B (40 bf16), A rows stride 80B
#define AP_XHI 0
#define AP_XLO 10240
#define AP_AHI 20480
#define AP_ALO 25600
#define AP_STG 30720
// bproj smem layout: H rows stride 144B (72 bf16), B rows stride 144B
#define BP_HHI 0
#define BP_HLO 18432
#define BP_BHI 36864
#define BP_BLO 46080
#define BP_TOT 55296

typedef unsigned long long ull;

#define LDSM4(r, a) asm volatile( \
    "ldmatrix.sync.aligned.m8n8.x4.shared.b16 {%0,%1,%2,%3}, [%4];" \
    : "=r"((r)[0]), "=r"((r)[1]), "=r"((r)[2]), "=r"((r)[3]) : "r"(a))

#define MMA(d, a, b) asm volatile( \
    "mma.sync.aligned.m16n8k16.row.col.f32.bf16.bf16.f32 " \
    "{%0,%1,%2,%3},{%4,%5,%6,%7},{%8,%9},{%0,%1,%2,%3};" \
    : "+f"((d)[0]), "+f"((d)[1]), "+f"((d)[2]), "+f"((d)[3]) \
    : "r"((a)[0]), "r"((a)[1]), "r"((a)[2]), "r"((a)[3]), "r"((b)[0]), "r"((b)[1]))

__device__ __forceinline__ uint32_t smem_u32(const void* p) {
    uint32_t a;
    asm("{.reg .u64 t; cvta.to.shared.u64 t, %1; cvt.u32.u64 %0, t;}" : "=r"(a) : "l"(p));
    return a;
}

// split (a,b) f32 pair -> packed bf16x2 hi + bf16x2 residual lo (lower half = a)
__device__ __forceinline__ void cvt_split(float a, float b, uint32_t& hi, uint32_t& lo) {
    asm("cvt.rn.bf16x2.f32 %0, %1, %2;" : "=r"(hi) : "f"(b), "f"(a));
    float fa = __uint_as_float(hi << 16);
    float fb = __uint_as_float(hi & 0xFFFF0000u);
    float ra = a - fa, rb = b - fb;
    asm("cvt.rn.bf16x2.f32 %0, %1, %2;" : "=r"(lo) : "f"(rb), "f"(ra));
}

// convert 8 consecutive f32 -> 16B hi + 16B lo smem stores
__device__ __forceinline__ void stage8(const float* src, char* hi_p, char* lo_p) {
    float4 v0 = *(const float4*)src;
    float4 v1 = *(const float4*)(src + 4);
    uint4 h, l;
    cvt_split(v0.x, v0.y, h.x, l.x);
    cvt_split(v0.z, v0.w, h.y, l.y);
    cvt_split(v1.x, v1.y, h.z, l.z);
    cvt_split(v1.z, v1.w, h.w, l.w);
    *(uint4*)hi_p = h;
    *(uint4*)lo_p = l;
}

// ---------------- scratch ----------------------------------------------------
__device__ float g_xmix[(size_t)TOK * H];
__device__ float g_hpart[KSPLIT][(size_t)TOK * R];
__device__ float g_h[(size_t)TOK * R];
__device__ float g_coef[TOK];
__device__ int   g_counts[E];
__device__ int   g_cnt[E];
__device__ int   g_tilestart[E + 1];
__device__ int   g_list[E * TOK];

// ---------------- bookkeeping ------------------------------------------------
__global__ void reset_kernel() {
    if (threadIdx.x < E) g_counts[threadIdx.x] = 0;
}

__global__ void plan_kernel() {
    if (threadIdx.x == 0) {
        int ts = 0;
        for (int e = 0; e < E; e++) {
            int c = g_counts[e];
            g_cnt[e] = c;
            g_tilestart[e] = ts;
            g_counts[e] = 0;
            ts += (c + TM - 1) / TM;
        }
        g_tilestart[E] = ts;
    }
}

// ---------------- fused residual-mix + gating + scatter (fp32, proven) -------
__global__ void __launch_bounds__(256) mix_gate_kernel(
    const float* __restrict__ xprev, const float* __restrict__ hx,
    const float* __restrict__ gw, const float* __restrict__ gates, int layer)
{
    int warp = threadIdx.x >> 5, lane = threadIdx.x & 31;
    int t = blockIdx.x * 8 + warp;

    float z = 1.0f / (1.0f + expf(-gates[layer]));
    float omz = 1.0f - z;

    const float* xp = xprev + (size_t)t * H;
    const float* hp = hx    + (size_t)t * H;
    float*       xm = g_xmix + (size_t)t * H;

    float acc[E];
#pragma unroll
    for (int e = 0; e < E; e++) acc[e] = 0.f;

#pragma unroll 4
    for (int j = 0; j < H / 128; j++) {
        int k = j * 128 + lane * 4;
        float4 a = *(const float4*)(xp + k);
        float4 b = *(const float4*)(hp + k);
        float4 v;
        v.x = z * a.x + omz * b.x;
        v.y = z * a.y + omz * b.y;
        v.z = z * a.z + omz * b.z;
        v.w = z * a.w + omz * b.w;
        *(float4*)(xm + k) = v;
#pragma unroll
        for (int e = 0; e < E; e++) {
            float4 w = *(const float4*)(gw + (size_t)e * H + k);
            acc[e] += v.x * w.x + v.y * w.y + v.z * w.z + v.w * w.w;
        }
    }
#pragma unroll
    for (int e = 0; e < E; e++)
#pragma unroll
        for (int o = 16; o > 0; o >>= 1)
            acc[e] += __shfl_xor_sync(0xffffffffu, acc[e], o);

    if (lane == 0) {
        float m = acc[0]; int g = 0;
#pragma unroll
        for (int e = 1; e < E; e++) if (acc[e] > m) { m = acc[e]; g = e; }
        float s = 0.f;
#pragma unroll
        for (int e = 0; e < E; e++) s += expf(acc[e] - m);
        g_coef[t] = SCALING / s;
        int pos = atomicAdd(&g_counts[g], 1);
        g_list[g * TOK + pos] = t;
    }
}

// ---------------- A projection: HMMA bf16 hi/lo split -------------------------
// Tile 128 tokens x 64 r, K-chunk 512 per part, BK=32, double-buffered staging.
__global__ void __launch_bounds__(128) aproj_kernel(const float* __restrict__ A)
{
    extern __shared__ __align__(16) char dsm[];
    __shared__ int s_tok[TM];

    int gt = blockIdx.x;
    if (gt >= g_tilestart[E]) return;
    int part = blockIdx.y;
    int e = 0;
    while (gt >= g_tilestart[e + 1]) e++;
    int tile = gt - g_tilestart[e];
    int cnt  = g_cnt[e];

    int tid = threadIdx.x, w = tid >> 5, lane = tid & 31;
    int idx = tile * TM + tid;
    s_tok[tid] = (idx < cnt) ? g_list[e * TOK + idx] : -1;
    __syncthreads();

    int tok = s_tok[tid];
    int ctok = (tok >= 0) ? tok : s_tok[0];
    const float* xsrc = g_xmix + (size_t)ctok * H + part * KCH;
    int ar = tid >> 1, ah = (tid & 1) << 4;
    const float* asrc = A + (size_t)e * R * H + (size_t)ar * H + part * KCH + ah;

    uint32_t sb = smem_u32(dsm);
    // ldmatrix lane addressing
    int rin = lane & 7;
    int xrow0 = w * 32 + ((lane >> 3) & 1) * 8 + rin;    // + mi*16
    int xko   = ((lane >> 4) & 1) * 8;
    int brow0 = ((lane >> 4) & 1) * 8 + rin;             // + nj*16
    int bko   = ((lane >> 3) & 1) * 8;

    float acc[2][8][4];
#pragma unroll
    for (int mi = 0; mi < 2; mi++)
#pragma unroll
        for (int nt = 0; nt < 8; nt++)
#pragma unroll
            for (int q = 0; q < 4; q++) acc[mi][nt][q] = 0.f;

    // stage chunk 0
    {
        char* xh = dsm + AP_XHI + tid * 80;
        char* xl = dsm + AP_XLO + tid * 80;
#pragma unroll
        for (int p = 0; p < 4; p++) stage8(xsrc + p * 8, xh + p * 16, xl + p * 16);
        char* bh = dsm + AP_AHI + ar * 80 + ah * 2;
        char* bl = dsm + AP_ALO + ar * 80 + ah * 2;
#pragma unroll
        for (int p = 0; p < 2; p++) stage8(asrc + p * 8, bh + p * 16, bl + p * 16);
    }
    __syncthreads();

#pragma unroll 1
    for (int kc = 0; kc < NC; kc++) {
        uint32_t stg = sb + (kc & 1) * AP_STG;
        // --- MMA on current stage ---
#pragma unroll
        for (int kh = 0; kh < 2; kh++) {
            uint32_t xh[2][4], xl[2][4];
#pragma unroll
            for (int mi = 0; mi < 2; mi++) {
                uint32_t ro = (uint32_t)(xrow0 + mi * 16) * 80 + (kh * 16 + xko) * 2;
                LDSM4(xh[mi], stg + AP_XHI + ro);
                LDSM4(xl[mi], stg + AP_XLO + ro);
            }
            uint32_t bh[8][2], bl[8][2];
#pragma unroll
            for (int nj = 0; nj < 4; nj++) {
                uint32_t ro = (uint32_t)(brow0 + nj * 16) * 80 + (kh * 16 + bko) * 2;
                uint32_t r[4];
                LDSM4(r, stg + AP_AHI + ro);
                bh[nj*2][0] = r[0]; bh[nj*2][1] = r[1];
                bh[nj*2+1][0] = r[2]; bh[nj*2+1][1] = r[3];
                LDSM4(r, stg + AP_ALO + ro);
                bl[nj*2][0] = r[0]; bl[nj*2][1] = r[1];
                bl[nj*2+1][0] = r[2]; bl[nj*2+1][1] = r[3];
            }
#pragma unroll
            for (int mi = 0; mi < 2; mi++)
#pragma unroll
                for (int nt = 0; nt < 8; nt++) {
                    MMA(acc[mi][nt], xh[mi], bh[nt]);
                    MMA(acc[mi][nt], xh[mi], bl[nt]);
                    MMA(acc[mi][nt], xl[mi], bh[nt]);
                }
        }
        // --- stage next chunk into other buffer ---
        if (kc + 1 < NC) {
            int kb = (kc + 1) * BK;
            char* base = dsm + ((kc + 1) & 1) * AP_STG;
            char* xh = base + AP_XHI + tid * 80;
            char* xl = base + AP_XLO + tid * 80;
#pragma unroll
            for (int p = 0; p < 4; p++) stage8(xsrc + kb + p * 8, xh + p * 16, xl + p * 16);
            char* bh = base + AP_AHI + ar * 80 + ah * 2;
            char* bl = base + AP_ALO + ar * 80 + ah * 2;
#pragma unroll
            for (int p = 0; p < 2; p++) stage8(asrc + kb + p * 8, bh + p * 16, bl + p * 16);
        }
        __syncthreads();
    }

    float* hp = g_hpart[part];
#pragma unroll
    for (int mi = 0; mi < 2; mi++) {
        int mg = w * 32 + mi * 16 + (lane >> 2);
        int t0 = s_tok[mg], t1 = s_tok[mg + 8];
#pragma unroll
        for (int nt = 0; nt < 8; nt++) {
            int n0 = nt * 8 + 2 * (lane & 3);
            if (t0 >= 0) *(float2*)&hp[(size_t)t0 * R + n0] = make_float2(acc[mi][nt][0], acc[mi][nt][1]);
            if (t1 >= 0) *(float2*)&hp[(size_t)t1 * R + n0] = make_float2(acc[mi][nt][2], acc[mi][nt][3]);
        }
    }
}

// ---------------- reduce 4 K-partials ----------------------------------------
__global__ void hreduce_kernel() {
    int i = blockIdx.x * 256 + threadIdx.x;
    float4 a = ((const float4*)g_hpart[0])[i];
    float4 b = ((const float4*)g_hpart[1])[i];
    float4 c = ((const float4*)g_hpart[2])[i];
    float4 d = ((const float4*)g_hpart[3])[i];
    float4 o;
    o.x = (a.x + b.x) + (c.x + d.x);
    o.y = (a.y + b.y) + (c.y + d.y);
    o.z = (a.z + b.z) + (c.z + d.z);
    o.w = (a.w + b.w) + (c.w + d.w);
    ((float4*)g_h)[i] = o;
}

// ---------------- B projection: HMMA bf16 hi/lo split -------------------------
// Tile 128 tokens x 64 h-cols, K = R = 64 single shot.
__global__ void __launch_bounds__(128) bproj_kernel(const float* __restrict__ Bm,
                                                    float* __restrict__ y)
{
    extern __shared__ __align__(16) char dsm[];
    __shared__ int s_tok[TM];

    int gt = blockIdx.x;
    if (gt >= g_tilestart[E]) return;
    int e = 0;
    while (gt >= g_tilestart[e + 1]) e++;
    int tile = gt - g_tilestart[e];
    int cnt  = g_cnt[e];
    int h0   = blockIdx.y * 64;

    int tid = threadIdx.x, w = tid >> 5, lane = tid & 31;
    int idx = tile * TM + tid;
    s_tok[tid] = (idx < cnt) ? g_list[e * TOK + idx] : -1;
    __syncthreads();

    // stage H (128 x 64) and Bm rows (64 x 64)
    {
        int tok = s_tok[tid];
        int ct = (tok >= 0) ? tok : s_tok[0];
        const float* hsrc = g_h + (size_t)ct * R;
        char* hh = dsm + BP_HHI + tid * 144;
        char* hl = dsm + BP_HLO + tid * 144;
#pragma unroll
        for (int p = 0; p < 8; p++) stage8(hsrc + p * 8, hh + p * 16, hl + p * 16);

        int br = tid >> 1, bo = (tid & 1) << 5;
        const float* bsrc = Bm + ((size_t)e * H + (size_t)(h0 + br)) * R + bo;
        char* bh = dsm + BP_BHI + br * 144 + bo * 2;
        char* bl = dsm + BP_BLO + br * 144 + bo * 2;
#pragma unroll
        for (int p = 0; p < 4; p++) stage8(bsrc + p * 8, bh + p * 16, bl + p * 16);
    }
    __syncthreads();

    uint32_t sb = smem_u32(dsm);
    int rin = lane & 7;
    int xrow0 = w * 32 + ((lane >> 3) & 1) * 8 + rin;
    int xko   = ((lane >> 4) & 1) * 8;
    int brow0 = ((lane >> 4) & 1) * 8 + rin;
    int bko   = ((lane >> 3) & 1) * 8;

    float acc[2][8][4];
#pragma unroll
    for (int mi = 0; mi < 2; mi++)
#pragma unroll
        for (int nt = 0; nt < 8; nt++)
#pragma unroll
            for (int q = 0; q < 4; q++) acc[mi][nt][q] = 0.f;

#pragma unroll
    for (int kh = 0; kh < 4; kh++) {
        uint32_t xh[2][4], xl[2][4];
#pragma unroll
        for (int mi = 0; mi < 2; mi++) {
            uint32_t ro = (uint32_t)(xrow0 + mi * 16) * 144 + (kh * 16 + xko) * 2;
            LDSM4(xh[mi], sb + BP_HHI + ro);
            LDSM4(xl[mi], sb + BP_HLO + ro);
        }
        uint32_t bh[8][2], bl[8][2];
#pragma unroll
        for (int nj = 0; nj < 4; nj++) {
            uint32_t ro = (uint32_t)(brow0 + nj * 16) * 144 + (kh * 16 + bko) * 2;
            uint32_t r[4];
            LDSM4(r, sb + BP_BHI + ro);
            bh[nj*2][0] = r[0]; bh[nj*2][1] = r[1];
            bh[nj*2+1][0] = r[2]; bh[nj*2+1][1] = r[3];
            LDSM4(r, sb + BP_BLO + ro);
            bl[nj*2][0] = r[0]; bl[nj*2][1] = r[1];
            bl[nj*2+1][0] = r[2]; bl[nj*2+1][1] = r[3];
        }
#pragma unroll
        for (int mi = 0; mi < 2; mi++)
#pragma unroll
            for (int nt = 0; nt < 8; nt++) {
                MMA(acc[mi][nt], xh[mi], bh[nt]);
                MMA(acc[mi][nt], xh[mi], bl[nt]);
                MMA(acc[mi][nt], xl[mi], bh[nt]);
            }
    }

#pragma unroll
    for (int mi = 0; mi < 2; mi++) {
        int mg = w * 32 + mi * 16 + (lane >> 2);
        int t0 = s_tok[mg], t1 = s_tok[mg + 8];
        float c0 = (t0 >= 0) ? g_coef[t0] : 0.f;
        float c1 = (t1 >= 0) ? g_coef[t1] : 0.f;
#pragma unroll
        for (int nt = 0; nt < 8; nt++) {
            int n0 = nt * 8 + 2 * (lane & 3);
            if (t0 >= 0)
                *(float2*)&y[(size_t)t0 * H + h0 + n0] =
                    make_float2(acc[mi][nt][0] * c0, acc[mi][nt][1] * c0);
            if (t1 >= 0)
                *(float2*)&y[(size_t)t1 * H + h0 + n0] =
                    make_float2(acc[mi][nt][2] * c1, acc[mi][nt][3] * c1);
        }
    }
}

// ---------------- launcher ----------------------------------------------------
extern "C" void kernel_launch(void* const* d_in, const int* in_sizes, int n_in,
                              void* d_out, int out_size)
{
    const float* hs    = (const float*)d_in[0];  // [L+1, B, S, H]
    const float* gates = (const float*)d_in[1];  // [L]
    const float* A     = (const float*)d_in[2];  // [L, E, R, H]
    const float* Bm    = (const float*)d_in[3];  // [L, E, H, R]
    const float* gw    = (const float*)d_in[4];  // [L, E, H]
    float* y = (float*)d_out;

    const size_t HS = (size_t)TOK * H;
    const int ASM = 2 * AP_STG;     // 61440
    const int BSM = BP_TOT;         // 55296

    cudaFuncSetAttribute(aproj_kernel, cudaFuncAttributeMaxDynamicSharedMemorySize, ASM);
    cudaFuncSetAttribute(bproj_kernel, cudaFuncAttributeMaxDynamicSharedMemorySize, BSM);

    reset_kernel<<<1, 32>>>();
    for (int i = 0; i < L; i++) {
        const float* xprev = (i == 0) ? hs : y;
        const float* hx    = hs + (size_t)((i == 0) ? 1 : i) * HS;

        mix_gate_kernel<<<TOK / 8, 256>>>(xprev, hx, gw + (size_t)i * E * H, gates, i);
        plan_kernel<<<1, 32>>>();
        aproj_kernel<<<dim3(NTILES, KSPLIT), 128, ASM>>>(A + (size_t)i * E * R * H);
        hreduce_kernel<<<TOK * R / 4 / 256, 256>>>();
        bproj_kernel<<<dim3(NTILES, H / 64), 128, BSM>>>(Bm + (size_t)i * E * H * R, y);
    }
}

// round 9
// speedup vs baseline: 1.4358x; 1.0139x over previous
#include <cuda_runtime.h>
#include <cuda_bf16.h>
#include <math.h>
#include <cstdint>

#define L 8
#define E 8
#define R 64
#define H 2048
#define TOK 8192
#define SCALING 0.5f

#define TM 128
#define KSPLIT 4
#define KCH (H / KSPLIT)     // 512
#define BK 32
#define NC (KCH / BK)        // 16
#define NTILES (TOK / TM + E)

// aproj smem (bytes/stage): X rows 80B stride, A rows 80B stride
#define AP_XHI 0
#define AP_XLO 10240
#define AP_AHI 20480
#define AP_ALO 25600
#define AP_STG 30720
// bproj smem: H rows 144B stride, B rows 144B stride
#define BP_HHI 0
#define BP_HLO 18432
#define BP_BHI 36864
#define BP_BLO 46080
#define BP_TOT 55296

#define NWA ((size_t)L * E * R * H)   // A elements (== Bm elements)

typedef unsigned long long ull;

#define LDSM4(r, a) asm volatile( \
    "ldmatrix.sync.aligned.m8n8.x4.shared.b16 {%0,%1,%2,%3}, [%4];" \
    : "=r"((r)[0]), "=r"((r)[1]), "=r"((r)[2]), "=r"((r)[3]) : "r"(a))

#define MMA(d, a, b) asm volatile( \
    "mma.sync.aligned.m16n8k16.row.col.f32.bf16.bf16.f32 " \
    "{%0,%1,%2,%3},{%4,%5,%6,%7},{%8,%9},{%0,%1,%2,%3};" \
    : "+f"((d)[0]), "+f"((d)[1]), "+f"((d)[2]), "+f"((d)[3]) \
    : "r"((a)[0]), "r"((a)[1]), "r"((a)[2]), "r"((a)[3]), "r"((b)[0]), "r"((b)[1]))

#define CP16(d, s)  asm volatile("cp.async.cg.shared.global [%0], [%1], 16;" :: "r"(d), "l"(s))
#define CPCOMMIT()  asm volatile("cp.async.commit_group;" ::: "memory")
#define CPWAIT1()   asm volatile("cp.async.wait_group 1;" ::: "memory")
#define CPWAIT0()   asm volatile("cp.async.wait_group 0;" ::: "memory")

__device__ __forceinline__ uint32_t smem_u32(const void* p) {
    uint32_t a;
    asm("{.reg .u64 t; cvta.to.shared.u64 t, %1; cvt.u32.u64 %0, t;}" : "=r"(a) : "l"(p));
    return a;
}

// split (a,b) f32 -> bf16x2 hi + bf16x2 residual lo
__device__ __forceinline__ void cvt_split(float a, float b, uint32_t& hi, uint32_t& lo) {
    asm("cvt.rn.bf16x2.f32 %0, %1, %2;" : "=r"(hi) : "f"(b), "f"(a));
    float fa = __uint_as_float(hi << 16);
    float fb = __uint_as_float(hi & 0xFFFF0000u);
    float ra = a - fa, rb = b - fb;
    asm("cvt.rn.bf16x2.f32 %0, %1, %2;" : "=r"(lo) : "f"(rb), "f"(ra));
}

// ---------------- scratch ----------------------------------------------------
__device__ uint16_t g_xh[(size_t)TOK * H];       // bf16 hi of mixed x
__device__ uint16_t g_xl[(size_t)TOK * H];       // bf16 lo
__device__ uint16_t g_ah[NWA], g_al[NWA];        // A weights hi/lo (all layers)
__device__ uint16_t g_bh[NWA], g_bl[NWA];        // Bm weights hi/lo
__device__ float    g_hpart[KSPLIT][(size_t)TOK * R];
__device__ uint16_t g_hh[(size_t)TOK * R];       // reduced h hi/lo
__device__ uint16_t g_hl[(size_t)TOK * R];
__device__ float    g_coef[TOK];
__device__ int      g_counts[E];
__device__ int      g_cnt[E];
__device__ int      g_tilestart[E + 1];
__device__ int      g_list[E * TOK];

// ---------------- prepass: weights f32 -> bf16 hi/lo (A and Bm) --------------
__global__ void __launch_bounds__(256) wconv_kernel(const float* __restrict__ A,
                                                    const float* __restrict__ Bm)
{
    if (blockIdx.x == 0 && threadIdx.x < E) g_counts[threadIdx.x] = 0;
    size_t i = (size_t)blockIdx.x * 256 + threadIdx.x;   // float4 index
    const size_t NA4 = NWA / 4;
    const float4* src;
    uint16_t *hd, *ld;
    size_t j = i;
    if (i < NA4) { src = (const float4*)A;  hd = g_ah; ld = g_al; }
    else         { src = (const float4*)Bm; hd = g_bh; ld = g_bl; j = i - NA4; }
    float4 v = src[j];
    uint2 h, l;
    cvt_split(v.x, v.y, h.x, l.x);
    cvt_split(v.z, v.w, h.y, l.y);
    ((uint2*)hd)[j] = h;
    ((uint2*)ld)[j] = l;
}

// ---------------- plan ---------------------------------------------------------
__global__ void plan_kernel() {
    if (threadIdx.x == 0) {
        int ts = 0;
        for (int e = 0; e < E; e++) {
            int c = g_counts[e];
            g_cnt[e] = c;
            g_tilestart[e] = ts;
            g_counts[e] = 0;
            ts += (c + TM - 1) / TM;
        }
        g_tilestart[E] = ts;
    }
}

// ---------------- fused mix + gating + scatter; emits bf16 hi/lo x -----------
__global__ void __launch_bounds__(256) mix_gate_kernel(
    const float* __restrict__ xprev, const float* __restrict__ hx,
    const float* __restrict__ gw, const float* __restrict__ gates, int layer)
{
    int warp = threadIdx.x >> 5, lane = threadIdx.x & 31;
    int t = blockIdx.x * 8 + warp;

    float z = 1.0f / (1.0f + expf(-gates[layer]));
    float omz = 1.0f - z;

    const float* xp = xprev + (size_t)t * H;
    const float* hp = hx    + (size_t)t * H;
    uint32_t* xh32 = (uint32_t*)(g_xh + (size_t)t * H);
    uint32_t* xl32 = (uint32_t*)(g_xl + (size_t)t * H);

    float acc[E];
#pragma unroll
    for (int e = 0; e < E; e++) acc[e] = 0.f;

#pragma unroll 4
    for (int j = 0; j < H / 128; j++) {
        int k = j * 128 + lane * 4;
        float4 a = *(const float4*)(xp + k);
        float4 b = *(const float4*)(hp + k);
        float4 v;
        v.x = z * a.x + omz * b.x;
        v.y = z * a.y + omz * b.y;
        v.z = z * a.z + omz * b.z;
        v.w = z * a.w + omz * b.w;
        uint2 hh, ll;
        cvt_split(v.x, v.y, hh.x, ll.x);
        cvt_split(v.z, v.w, hh.y, ll.y);
        *(uint2*)(xh32 + k / 2) = hh;
        *(uint2*)(xl32 + k / 2) = ll;
#pragma unroll
        for (int e = 0; e < E; e++) {
            float4 w = *(const float4*)(gw + (size_t)e * H + k);
            acc[e] += v.x * w.x + v.y * w.y + v.z * w.z + v.w * w.w;
        }
    }
#pragma unroll
    for (int e = 0; e < E; e++)
#pragma unroll
        for (int o = 16; o > 0; o >>= 1)
            acc[e] += __shfl_xor_sync(0xffffffffu, acc[e], o);

    if (lane == 0) {
        float m = acc[0]; int g = 0;
#pragma unroll
        for (int e = 1; e < E; e++) if (acc[e] > m) { m = acc[e]; g = e; }
        float s = 0.f;
#pragma unroll
        for (int e = 0; e < E; e++) s += expf(acc[e] - m);
        g_coef[t] = SCALING / s;
        int pos = atomicAdd(&g_counts[g], 1);
        g_list[g * TOK + pos] = t;
    }
}

// ---------------- A projection: cp.async staging + HMMA -----------------------
__global__ void __launch_bounds__(128) aproj_kernel(int layer)
{
    extern __shared__ __align__(16) char dsm[];
    __shared__ int s_tok[TM];

    int gt = blockIdx.x;
    if (gt >= g_tilestart[E]) return;
    int part = blockIdx.y;
    int e = 0;
    while (gt >= g_tilestart[e + 1]) e++;
    int tile = gt - g_tilestart[e];
    int cnt  = g_cnt[e];

    int tid = threadIdx.x, w = tid >> 5, lane = tid & 31;
    int idx = tile * TM + tid;
    s_tok[tid] = (idx < cnt) ? g_list[e * TOK + idx] : -1;
    __syncthreads();

    int tok = s_tok[tid];
    int ctok = (tok >= 0) ? tok : s_tok[0];
    const uint16_t* xhs = g_xh + (size_t)ctok * H + part * KCH;
    const uint16_t* xls = g_xl + (size_t)ctok * H + part * KCH;
    int ar = tid >> 1, ah = (tid & 1) << 4;   // 2 threads/row, 16 bf16 each
    size_t aoff = (((size_t)layer * E + e) * R + ar) * H + part * KCH + ah;
    const uint16_t* ahs = g_ah + aoff;
    const uint16_t* als = g_al + aoff;

    uint32_t sb = smem_u32(dsm);
    uint32_t xhd = sb + AP_XHI + tid * 80;
    uint32_t xld = sb + AP_XLO + tid * 80;
    uint32_t ahd = sb + AP_AHI + ar * 80 + ah * 2;
    uint32_t ald = sb + AP_ALO + ar * 80 + ah * 2;

#define ASTAGE(kb, soff) do {                                          \
        _Pragma("unroll")                                              \
        for (int q = 0; q < 4; q++) {                                  \
            CP16(xhd + (soff) + q * 16, xhs + (kb) + q * 8);           \
            CP16(xld + (soff) + q * 16, xls + (kb) + q * 8);           \
        }                                                              \
        _Pragma("unroll")                                              \
        for (int q = 0; q < 2; q++) {                                  \
            CP16(ahd + (soff) + q * 16, ahs + (kb) + q * 8);           \
            CP16(ald + (soff) + q * 16, als + (kb) + q * 8);           \
        }                                                              \
        CPCOMMIT();                                                    \
    } while (0)

    ASTAGE(0, 0);

    int rin = lane & 7;
    int xrow0 = w * 32 + ((lane >> 3) & 1) * 8 + rin;
    int xko   = ((lane >> 4) & 1) * 8;
    int brow0 = ((lane >> 4) & 1) * 8 + rin;
    int bko   = ((lane >> 3) & 1) * 8;

    float acc[2][8][4];
#pragma unroll
    for (int mi = 0; mi < 2; mi++)
#pragma unroll
        for (int nt = 0; nt < 8; nt++)
#pragma unroll
            for (int q = 0; q < 4; q++) acc[mi][nt][q] = 0.f;

#pragma unroll 1
    for (int kc = 0; kc < NC; kc++) {
        int nk = (kc + 1 < NC) ? (kc + 1) : (NC - 1);
        ASTAGE(nk * BK, ((kc + 1) & 1) * AP_STG);
        CPWAIT1();
        __syncthreads();

        uint32_t stg = sb + (kc & 1) * AP_STG;
#pragma unroll
        for (int kh = 0; kh < 2; kh++) {
            uint32_t xh[2][4], xl[2][4];
#pragma unroll
            for (int mi = 0; mi < 2; mi++) {
                uint32_t ro = (uint32_t)(xrow0 + mi * 16) * 80 + (kh * 16 + xko) * 2;
                LDSM4(xh[mi], stg + AP_XHI + ro);
                LDSM4(xl[mi], stg + AP_XLO + ro);
            }
            uint32_t bh[8][2], bl[8][2];
#pragma unroll
            for (int nj = 0; nj < 4; nj++) {
                uint32_t ro = (uint32_t)(brow0 + nj * 16) * 80 + (kh * 16 + bko) * 2;
                uint32_t r[4];
                LDSM4(r, stg + AP_AHI + ro);
                bh[nj*2][0] = r[0]; bh[nj*2][1] = r[1];
                bh[nj*2+1][0] = r[2]; bh[nj*2+1][1] = r[3];
                LDSM4(r, stg + AP_ALO + ro);
                bl[nj*2][0] = r[0]; bl[nj*2][1] = r[1];
                bl[nj*2+1][0] = r[2]; bl[nj*2+1][1] = r[3];
            }
#pragma unroll
            for (int mi = 0; mi < 2; mi++)
#pragma unroll
                for (int nt = 0; nt < 8; nt++) {
                    MMA(acc[mi][nt], xh[mi], bh[nt]);
                    MMA(acc[mi][nt], xh[mi], bl[nt]);
                    MMA(acc[mi][nt], xl[mi], bh[nt]);
                }
        }
        __syncthreads();
    }
#undef ASTAGE

    float* hp = g_hpart[part];
#pragma unroll
    for (int mi = 0; mi < 2; mi++) {
        int mg = w * 32 + mi * 16 + (lane >> 2);
        int t0 = s_tok[mg], t1 = s_tok[mg + 8];
#pragma unroll
        for (int nt = 0; nt < 8; nt++) {
            int n0 = nt * 8 + 2 * (lane & 3);
            if (t0 >= 0) *(float2*)&hp[(size_t)t0 * R + n0] = make_float2(acc[mi][nt][0], acc[mi][nt][1]);
            if (t1 >= 0) *(float2*)&hp[(size_t)t1 * R + n0] = make_float2(acc[mi][nt][2], acc[mi][nt][3]);
        }
    }
}

// ---------------- reduce 4 partials -> bf16 hi/lo h ---------------------------
__global__ void hreduce_kernel() {
    int i = blockIdx.x * 256 + threadIdx.x;
    float4 a = ((const float4*)g_hpart[0])[i];
    float4 b = ((const float4*)g_hpart[1])[i];
    float4 c = ((const float4*)g_hpart[2])[i];
    float4 d = ((const float4*)g_hpart[3])[i];
    float4 o;
    o.x = (a.x + b.x) + (c.x + d.x);
    o.y = (a.y + b.y) + (c.y + d.y);
    o.z = (a.z + b.z) + (c.z + d.z);
    o.w = (a.w + b.w) + (c.w + d.w);
    uint2 h, l;
    cvt_split(o.x, o.y, h.x, l.x);
    cvt_split(o.z, o.w, h.y, l.y);
    ((uint2*)g_hh)[i] = h;
    ((uint2*)g_hl)[i] = l;
}

// ---------------- B projection: cp.async staging + HMMA -----------------------
__global__ void __launch_bounds__(128) bproj_kernel(int layer, float* __restrict__ y)
{
    extern __shared__ __align__(16) char dsm[];
    __shared__ int s_tok[TM];

    int gt = blockIdx.x;
    if (gt >= g_tilestart[E]) return;
    int e = 0;
    while (gt >= g_tilestart[e + 1]) e++;
    int tile = gt - g_tilestart[e];
    int cnt  = g_cnt[e];
    int h0   = blockIdx.y * 64;

    int tid = threadIdx.x, w = tid >> 5, lane = tid & 31;
    int idx = tile * TM + tid;
    s_tok[tid] = (idx < cnt) ? g_list[e * TOK + idx] : -1;
    __syncthreads();

    uint32_t sb = smem_u32(dsm);
    {
        int tok = s_tok[tid];
        int ct = (tok >= 0) ? tok : s_tok[0];
        const uint16_t* hhs = g_hh + (size_t)ct * R;
        const uint16_t* hls = g_hl + (size_t)ct * R;
        uint32_t hhd = sb + BP_HHI + tid * 144;
        uint32_t hld = sb + BP_HLO + tid * 144;
#pragma unroll
        for (int q = 0; q < 8; q++) {
            CP16(hhd + q * 16, hhs + q * 8);
            CP16(hld + q * 16, hls + q * 8);
        }
        int br = tid >> 1, bo = (tid & 1) << 5;    // 2 threads/row, 32 bf16 each
        size_t boff = (((size_t)layer * E + e) * H + (size_t)(h0 + br)) * R + bo;
        const uint16_t* bhs = g_bh + boff;
        const uint16_t* bls = g_bl + boff;
        uint32_t bhd = sb + BP_BHI + br * 144 + bo * 2;
        uint32_t bld = sb + BP_BLO + br * 144 + bo * 2;
#pragma unroll
        for (int q = 0; q < 4; q++) {
            CP16(bhd + q * 16, bhs + q * 8);
            CP16(bld + q * 16, bls + q * 8);
        }
        CPCOMMIT();
        CPWAIT0();
    }
    __syncthreads();

    int rin = lane & 7;
    int xrow0 = w * 32 + ((lane >> 3) & 1) * 8 + rin;
    int xko   = ((lane >> 4) & 1) * 8;
    int brow0 = ((lane >> 4) & 1) * 8 + rin;
    int bko   = ((lane >> 3) & 1) * 8;

    float acc[2][8][4];
#pragma unroll
    for (int mi = 0; mi < 2; mi++)
#pragma unroll
        for (int nt = 0; nt < 8; nt++)
#pragma unroll
            for (int q = 0; q < 4; q++) acc[mi][nt][q] = 0.f;

#pragma unroll
    for (int kh = 0; kh < 4; kh++) {
        uint32_t xh[2][4], xl[2][4];
#pragma unroll
        for (int mi = 0; mi < 2; mi++) {
            uint32_t ro = (uint32_t)(xrow0 + mi * 16) * 144 + (kh * 16 + xko) * 2;
            LDSM4(xh[mi], sb + BP_HHI + ro);
            LDSM4(xl[mi], sb + BP_HLO + ro);
        }
        uint32_t bh[8][2], bl[8][2];
#pragma unroll
        for (int nj = 0; nj < 4; nj++) {
            uint32_t ro = (uint32_t)(brow0 + nj * 16) * 144 + (kh * 16 + bko) * 2;
            uint32_t r[4];
            LDSM4(r, sb + BP_BHI + ro);
            bh[nj*2][0] = r[0]; bh[nj*2][1] = r[1];
            bh[nj*2+1][0] = r[2]; bh[nj*2+1][1] = r[3];
            LDSM4(r, sb + BP_BLO + ro);
            bl[nj*2][0] = r[0]; bl[nj*2][1] = r[1];
            bl[nj*2+1][0] = r[2]; bl[nj*2+1][1] = r[3];
        }
#pragma unroll
        for (int mi = 0; mi < 2; mi++)
#pragma unroll
            for (int nt = 0; nt < 8; nt++) {
                MMA(acc[mi][nt], xh[mi], bh[nt]);
                MMA(acc[mi][nt], xh[mi], bl[nt]);
                MMA(acc[mi][nt], xl[mi], bh[nt]);
            }
    }

#pragma unroll
    for (int mi = 0; mi < 2; mi++) {
        int mg = w * 32 + mi * 16 + (lane >> 2);
        int t0 = s_tok[mg], t1 = s_tok[mg + 8];
        float c0 = (t0 >= 0) ? g_coef[t0] : 0.f;
        float c1 = (t1 >= 0) ? g_coef[t1] : 0.f;
#pragma unroll
        for (int nt = 0; nt < 8; nt++) {
            int n0 = nt * 8 + 2 * (lane & 3);
            if (t0 >= 0)
                *(float2*)&y[(size_t)t0 * H + h0 + n0] =
                    make_float2(acc[mi][nt][0] * c0, acc[mi][nt][1] * c0);
            if (t1 >= 0)
                *(float2*)&y[(size_t)t1 * H + h0 + n0] =
                    make_float2(acc[mi][nt][2] * c1, acc[mi][nt][3] * c1);
        }
    }
}

// ---------------- launcher ----------------------------------------------------
extern "C" void kernel_launch(void* const* d_in, const int* in_sizes, int n_in,
                              void* d_out, int out_size)
{
    const float* hs    = (const float*)d_in[0];
    const float* gates = (const float*)d_in[1];
    const float* A     = (const float*)d_in[2];
    const float* Bm    = (const float*)d_in[3];
    const float* gw    = (const float*)d_in[4];
    float* y = (float*)d_out;

    const size_t HS = (size_t)TOK * H;
    const int ASM = 2 * AP_STG;     // 61440
    const int BSM = BP_TOT;         // 55296

    cudaFuncSetAttribute(aproj_kernel, cudaFuncAttributeMaxDynamicSharedMemorySize, ASM);
    cudaFuncSetAttribute(bproj_kernel, cudaFuncAttributeMaxDynamicSharedMemorySize, BSM);

    wconv_kernel<<<(int)(2 * NWA / 4 / 256), 256>>>(A, Bm);   // also zeroes g_counts
    for (int i = 0; i < L; i++) {
        const float* xprev = (i == 0) ? hs : y;
        const float* hx    = hs + (size_t)((i == 0) ? 1 : i) * HS;

        mix_gate_kernel<<<TOK / 8, 256>>>(xprev, hx, gw + (size_t)i * E * H, gates, i);
        plan_kernel<<<1, 32>>>();
        aproj_kernel<<<dim3(NTILES, KSPLIT), 128, ASM>>>(i);
        hreduce_kernel<<<TOK * R / 4 / 256, 256>>>();
        bproj_kernel<<<dim3(NTILES, H / 64), 128, BSM>>>(i, y);
    }
}

// round 10
// speedup vs baseline: 1.5560x; 1.0837x over previous
#include <cuda_runtime.h>
#include <cuda_bf16.h>
#include <math.h>
#include <cstdint>

#define L 8
#define E 8
#define R 64
#define H 2048
#define TOK 8192
#define SCALING 0.5f

#define TM 128
#define KSPLIT 4
#define KCH (H / KSPLIT)     // 512
#define BK 32
#define NC (KCH / BK)        // 16
#define NTILES (TOK / TM + E)

// aproj smem (bytes/stage): X rows 80B stride, A rows 80B stride
#define AP_XHI 0
#define AP_XLO 10240
#define AP_AHI 20480
#define AP_ALO 25600
#define AP_STG 30720
// bproj smem: H rows 144B stride, B rows 144B stride
#define BP_HHI 0
#define BP_HLO 18432
#define BP_BHI 36864
#define BP_BLO 46080
#define BP_TOT 55296

#define NWA ((size_t)L * E * R * H)

typedef unsigned long long ull;

#define LDSM4(r, a) asm volatile( \
    "ldmatrix.sync.aligned.m8n8.x4.shared.b16 {%0,%1,%2,%3}, [%4];" \
    : "=r"((r)[0]), "=r"((r)[1]), "=r"((r)[2]), "=r"((r)[3]) : "r"(a))

#define MMA(d, a, b) asm volatile( \
    "mma.sync.aligned.m16n8k16.row.col.f32.bf16.bf16.f32 " \
    "{%0,%1,%2,%3},{%4,%5,%6,%7},{%8,%9},{%0,%1,%2,%3};" \
    : "+f"((d)[0]), "+f"((d)[1]), "+f"((d)[2]), "+f"((d)[3]) \
    : "r"((a)[0]), "r"((a)[1]), "r"((a)[2]), "r"((a)[3]), "r"((b)[0]), "r"((b)[1]))

#define CP16(d, s)  asm volatile("cp.async.cg.shared.global [%0], [%1], 16;" :: "r"(d), "l"(s))
#define CPCOMMIT()  asm volatile("cp.async.commit_group;" ::: "memory")
#define CPWAIT1()   asm volatile("cp.async.wait_group 1;" ::: "memory")
#define CPWAIT0()   asm volatile("cp.async.wait_group 0;" ::: "memory")

__device__ __forceinline__ uint32_t smem_u32(const void* p) {
    uint32_t a;
    asm("{.reg .u64 t; cvta.to.shared.u64 t, %1; cvt.u32.u64 %0, t;}" : "=r"(a) : "l"(p));
    return a;
}

__device__ __forceinline__ void cvt_split(float a, float b, uint32_t& hi, uint32_t& lo) {
    asm("cvt.rn.bf16x2.f32 %0, %1, %2;" : "=r"(hi) : "f"(b), "f"(a));
    float fa = __uint_as_float(hi << 16);
    float fb = __uint_as_float(hi & 0xFFFF0000u);
    float ra = a - fa, rb = b - fb;
    asm("cvt.rn.bf16x2.f32 %0, %1, %2;" : "=r"(lo) : "f"(rb), "f"(ra));
}

// ---------------- scratch ----------------------------------------------------
__device__ uint16_t g_xh[(size_t)TOK * H];
__device__ uint16_t g_xl[(size_t)TOK * H];
__device__ uint16_t g_ah[NWA], g_al[NWA];
__device__ uint16_t g_bh[NWA], g_bl[NWA];
__device__ float    g_hpart[KSPLIT][(size_t)TOK * R];
__device__ uint16_t g_hh[(size_t)TOK * R];
__device__ uint16_t g_hl[(size_t)TOK * R];
__device__ float    g_coef[TOK];
__device__ int      g_counts[E];
__device__ int      g_cnt[E];
__device__ int      g_tilestart[E + 1];
__device__ int      g_list[E * TOK];

// ---------------- prepass: weights f32 -> bf16 hi/lo --------------------------
__global__ void __launch_bounds__(256) wconv_kernel(const float* __restrict__ A,
                                                    const float* __restrict__ Bm)
{
    if (blockIdx.x == 0 && threadIdx.x < E) g_counts[threadIdx.x] = 0;
    size_t i = (size_t)blockIdx.x * 256 + threadIdx.x;
    const size_t NA4 = NWA / 4;
    const float4* src;
    uint16_t *hd, *ld;
    size_t j = i;
    if (i < NA4) { src = (const float4*)A;  hd = g_ah; ld = g_al; }
    else         { src = (const float4*)Bm; hd = g_bh; ld = g_bl; j = i - NA4; }
    float4 v = src[j];
    uint2 h, l;
    cvt_split(v.x, v.y, h.x, l.x);
    cvt_split(v.z, v.w, h.y, l.y);
    ((uint2*)hd)[j] = h;
    ((uint2*)ld)[j] = l;
}

__global__ void plan_kernel() {
    if (threadIdx.x == 0) {
        int ts = 0;
        for (int e = 0; e < E; e++) {
            int c = g_counts[e];
            g_cnt[e] = c;
            g_tilestart[e] = ts;
            g_counts[e] = 0;
            ts += (c + TM - 1) / TM;
        }
        g_tilestart[E] = ts;
    }
}

// ---------------- fused mix + gating + scatter --------------------------------
__global__ void __launch_bounds__(256) mix_gate_kernel(
    const float* __restrict__ xprev, const float* __restrict__ hx,
    const float* __restrict__ gw, const float* __restrict__ gates, int layer)
{
    int warp = threadIdx.x >> 5, lane = threadIdx.x & 31;
    int t = blockIdx.x * 8 + warp;

    float z = 1.0f / (1.0f + expf(-gates[layer]));
    float omz = 1.0f - z;

    const float* xp = xprev + (size_t)t * H;
    const float* hp = hx    + (size_t)t * H;
    uint32_t* xh32 = (uint32_t*)(g_xh + (size_t)t * H);
    uint32_t* xl32 = (uint32_t*)(g_xl + (size_t)t * H);

    float acc[E];
#pragma unroll
    for (int e = 0; e < E; e++) acc[e] = 0.f;

#pragma unroll 4
    for (int j = 0; j < H / 128; j++) {
        int k = j * 128 + lane * 4;
        float4 a = *(const float4*)(xp + k);
        float4 b = *(const float4*)(hp + k);
        float4 v;
        v.x = z * a.x + omz * b.x;
        v.y = z * a.y + omz * b.y;
        v.z = z * a.z + omz * b.z;
        v.w = z * a.w + omz * b.w;
        uint2 hh, ll;
        cvt_split(v.x, v.y, hh.x, ll.x);
        cvt_split(v.z, v.w, hh.y, ll.y);
        *(uint2*)(xh32 + k / 2) = hh;
        *(uint2*)(xl32 + k / 2) = ll;
#pragma unroll
        for (int e = 0; e < E; e++) {
            float4 w = *(const float4*)(gw + (size_t)e * H + k);
            acc[e] += v.x * w.x + v.y * w.y + v.z * w.z + v.w * w.w;
        }
    }
#pragma unroll
    for (int e = 0; e < E; e++)
#pragma unroll
        for (int o = 16; o > 0; o >>= 1)
            acc[e] += __shfl_xor_sync(0xffffffffu, acc[e], o);

    if (lane == 0) {
        float m = acc[0]; int g = 0;
#pragma unroll
        for (int e = 1; e < E; e++) if (acc[e] > m) { m = acc[e]; g = e; }
        float s = 0.f;
#pragma unroll
        for (int e = 0; e < E; e++) s += expf(acc[e] - m);
        g_coef[t] = SCALING / s;
        int pos = atomicAdd(&g_counts[g], 1);
        g_list[g * TOK + pos] = t;
    }
}

// ---------------- A projection: 256 threads, warp-M=16, HMMA ------------------
__global__ void __launch_bounds__(256) aproj_kernel(int layer)
{
    extern __shared__ __align__(16) char dsm[];
    __shared__ int s_tok[TM];

    int gt = blockIdx.x;
    if (gt >= g_tilestart[E]) return;
    int part = blockIdx.y;
    int e = 0;
    while (gt >= g_tilestart[e + 1]) e++;
    int tile = gt - g_tilestart[e];
    int cnt  = g_cnt[e];

    int tid = threadIdx.x, w = tid >> 5, lane = tid & 31;
    if (tid < TM) {
        int idx = tile * TM + tid;
        s_tok[tid] = (idx < cnt) ? g_list[e * TOK + idx] : -1;
    }
    __syncthreads();

    // staging roles: X row per 2 threads (16 bf16 each), A row per 4 threads (8 bf16)
    int xr = tid >> 1, xc = (tid & 1) << 4;
    int xtok = s_tok[xr];
    int cx = (xtok >= 0) ? xtok : s_tok[0];
    const uint16_t* xhs = g_xh + (size_t)cx * H + part * KCH + xc;
    const uint16_t* xls = g_xl + (size_t)cx * H + part * KCH + xc;
    int ar = tid >> 2, ac = (tid & 3) << 3;
    size_t aoff = (((size_t)layer * E + e) * R + ar) * H + part * KCH + ac;
    const uint16_t* ahs = g_ah + aoff;
    const uint16_t* als = g_al + aoff;

    uint32_t sb = smem_u32(dsm);
    uint32_t xhd = sb + AP_XHI + xr * 80 + xc * 2;
    uint32_t xld = sb + AP_XLO + xr * 80 + xc * 2;
    uint32_t ahd = sb + AP_AHI + ar * 80 + ac * 2;
    uint32_t ald = sb + AP_ALO + ar * 80 + ac * 2;

#define ASTAGE(kb, soff) do {                                  \
        CP16(xhd + (soff),      xhs + (kb));                   \
        CP16(xhd + (soff) + 16, xhs + (kb) + 8);               \
        CP16(xld + (soff),      xls + (kb));                   \
        CP16(xld + (soff) + 16, xls + (kb) + 8);               \
        CP16(ahd + (soff),      ahs + (kb));                   \
        CP16(ald + (soff),      als + (kb));                   \
        CPCOMMIT();                                            \
    } while (0)

    ASTAGE(0, 0);

    int rin = lane & 7;
    int xrow = w * 16 + ((lane >> 3) & 1) * 8 + rin;
    int xko  = ((lane >> 4) & 1) * 8;
    int brow0 = ((lane >> 4) & 1) * 8 + rin;
    int bko   = ((lane >> 3) & 1) * 8;

    float acc[8][4];
#pragma unroll
    for (int nt = 0; nt < 8; nt++)
#pragma unroll
        for (int q = 0; q < 4; q++) acc[nt][q] = 0.f;

#pragma unroll 1
    for (int kc = 0; kc < NC; kc++) {
        int nk = (kc + 1 < NC) ? (kc + 1) : (NC - 1);
        ASTAGE(nk * BK, ((kc + 1) & 1) * AP_STG);
        CPWAIT1();
        __syncthreads();

        uint32_t stg = sb + (kc & 1) * AP_STG;
#pragma unroll
        for (int kh = 0; kh < 2; kh++) {
            uint32_t xh[4], xl[4];
            uint32_t ro = (uint32_t)xrow * 80 + (kh * 16 + xko) * 2;
            LDSM4(xh, stg + AP_XHI + ro);
            LDSM4(xl, stg + AP_XLO + ro);
            uint32_t bh[8][2], bl[8][2];
#pragma unroll
            for (int nj = 0; nj < 4; nj++) {
                uint32_t bo = (uint32_t)(brow0 + nj * 16) * 80 + (kh * 16 + bko) * 2;
                uint32_t r[4];
                LDSM4(r, stg + AP_AHI + bo);
                bh[nj*2][0] = r[0]; bh[nj*2][1] = r[1];
                bh[nj*2+1][0] = r[2]; bh[nj*2+1][1] = r[3];
                LDSM4(r, stg + AP_ALO + bo);
                bl[nj*2][0] = r[0]; bl[nj*2][1] = r[1];
                bl[nj*2+1][0] = r[2]; bl[nj*2+1][1] = r[3];
            }
#pragma unroll
            for (int nt = 0; nt < 8; nt++) {
                MMA(acc[nt], xh, bh[nt]);
                MMA(acc[nt], xh, bl[nt]);
                MMA(acc[nt], xl, bh[nt]);
            }
        }
        __syncthreads();
    }
#undef ASTAGE

    float* hp = g_hpart[part];
    int mg = w * 16 + (lane >> 2);
    int t0 = s_tok[mg], t1 = s_tok[mg + 8];
#pragma unroll
    for (int nt = 0; nt < 8; nt++) {
        int n0 = nt * 8 + 2 * (lane & 3);
        if (t0 >= 0) *(float2*)&hp[(size_t)t0 * R + n0] = make_float2(acc[nt][0], acc[nt][1]);
        if (t1 >= 0) *(float2*)&hp[(size_t)t1 * R + n0] = make_float2(acc[nt][2], acc[nt][3]);
    }
}

// ---------------- reduce 4 partials -> bf16 hi/lo ------------------------------
__global__ void hreduce_kernel() {
    int i = blockIdx.x * 256 + threadIdx.x;
    float4 a = ((const float4*)g_hpart[0])[i];
    float4 b = ((const float4*)g_hpart[1])[i];
    float4 c = ((const float4*)g_hpart[2])[i];
    float4 d = ((const float4*)g_hpart[3])[i];
    float4 o;
    o.x = (a.x + b.x) + (c.x + d.x);
    o.y = (a.y + b.y) + (c.y + d.y);
    o.z = (a.z + b.z) + (c.z + d.z);
    o.w = (a.w + b.w) + (c.w + d.w);
    uint2 h, l;
    cvt_split(o.x, o.y, h.x, l.x);
    cvt_split(o.z, o.w, h.y, l.y);
    ((uint2*)g_hh)[i] = h;
    ((uint2*)g_hl)[i] = l;
}

// ---------------- B projection: 256 threads, warp-M=16, HMMA -------------------
__global__ void __launch_bounds__(256) bproj_kernel(int layer, float* __restrict__ y)
{
    extern __shared__ __align__(16) char dsm[];
    __shared__ int s_tok[TM];

    int gt = blockIdx.x;
    if (gt >= g_tilestart[E]) return;
    int e = 0;
    while (gt >= g_tilestart[e + 1]) e++;
    int tile = gt - g_tilestart[e];
    int cnt  = g_cnt[e];
    int h0   = blockIdx.y * 64;

    int tid = threadIdx.x, w = tid >> 5, lane = tid & 31;
    if (tid < TM) {
        int idx = tile * TM + tid;
        s_tok[tid] = (idx < cnt) ? g_list[e * TOK + idx] : -1;
    }
    __syncthreads();

    uint32_t sb = smem_u32(dsm);
    {
        // H: 128 rows x 64 bf16; 2 threads/row, 32 bf16 (64B) each
        int hr = tid >> 1, hc = (tid & 1) << 5;
        int htok = s_tok[hr];
        int ct = (htok >= 0) ? htok : s_tok[0];
        const uint16_t* hhs = g_hh + (size_t)ct * R + hc;
        const uint16_t* hls = g_hl + (size_t)ct * R + hc;
        uint32_t hhd = sb + BP_HHI + hr * 144 + hc * 2;
        uint32_t hld = sb + BP_HLO + hr * 144 + hc * 2;
#pragma unroll
        for (int q = 0; q < 4; q++) {
            CP16(hhd + q * 16, hhs + q * 8);
            CP16(hld + q * 16, hls + q * 8);
        }
        // B: 64 rows x 64 bf16; 4 threads/row, 16 bf16 (32B) each
        int br = tid >> 2, bc = (tid & 3) << 4;
        size_t boff = (((size_t)layer * E + e) * H + (size_t)(h0 + br)) * R + bc;
        const uint16_t* bhs = g_bh + boff;
        const uint16_t* bls = g_bl + boff;
        uint32_t bhd = sb + BP_BHI + br * 144 + bc * 2;
        uint32_t bld = sb + BP_BLO + br * 144 + bc * 2;
#pragma unroll
        for (int q = 0; q < 2; q++) {
            CP16(bhd + q * 16, bhs + q * 8);
            CP16(bld + q * 16, bls + q * 8);
        }
        CPCOMMIT();
        CPWAIT0();
    }
    __syncthreads();

    int rin = lane & 7;
    int xrow = w * 16 + ((lane >> 3) & 1) * 8 + rin;
    int xko  = ((lane >> 4) & 1) * 8;
    int brow0 = ((lane >> 4) & 1) * 8 + rin;
    int bko   = ((lane >> 3) & 1) * 8;

    float acc[8][4];
#pragma unroll
    for (int nt = 0; nt < 8; nt++)
#pragma unroll
        for (int q = 0; q < 4; q++) acc[nt][q] = 0.f;

#pragma unroll
    for (int kh = 0; kh < 4; kh++) {
        uint32_t xh[4], xl[4];
        uint32_t ro = (uint32_t)xrow * 144 + (kh * 16 + xko) * 2;
        LDSM4(xh, sb + BP_HHI + ro);
        LDSM4(xl, sb + BP_HLO + ro);
        uint32_t bh[8][2], bl[8][2];
#pragma unroll
        for (int nj = 0; nj < 4; nj++) {
            uint32_t bo = (uint32_t)(brow0 + nj * 16) * 144 + (kh * 16 + bko) * 2;
            uint32_t r[4];
            LDSM4(r, sb + BP_BHI + bo);
            bh[nj*2][0] = r[0]; bh[nj*2][1] = r[1];
            bh[nj*2+1][0] = r[2]; bh[nj*2+1][1] = r[3];
            LDSM4(r, sb + BP_BLO + bo);
            bl[nj*2][0] = r[0]; bl[nj*2][1] = r[1];
            bl[nj*2+1][0] = r[2]; bl[nj*2+1][1] = r[3];
        }
#pragma unroll
        for (int nt = 0; nt < 8; nt++) {
            MMA(acc[nt], xh, bh[nt]);
            MMA(acc[nt], xh, bl[nt]);
            MMA(acc[nt], xl, bh[nt]);
        }
    }

    int mg = w * 16 + (lane >> 2);
    int t0 = s_tok[mg], t1 = s_tok[mg + 8];
    float c0 = (t0 >= 0) ? g_coef[t0] : 0.f;
    float c1 = (t1 >= 0) ? g_coef[t1] : 0.f;
#pragma unroll
    for (int nt = 0; nt < 8; nt++) {
        int n0 = nt * 8 + 2 * (lane & 3);
        if (t0 >= 0)
            *(float2*)&y[(size_t)t0 * H + h0 + n0] =
                make_float2(acc[nt][0] * c0, acc[nt][1] * c0);
        if (t1 >= 0)
            *(float2*)&y[(size_t)t1 * H + h0 + n0] =
                make_float2(acc[nt][2] * c1, acc[nt][3] * c1);
    }
}

// ---------------- launcher ------------------------------------------------------
extern "C" void kernel_launch(void* const* d_in, const int* in_sizes, int n_in,
                              void* d_out, int out_size)
{
    const float* hs    = (const float*)d_in[0];
    const float* gates = (const float*)d_in[1];
    const float* A     = (const float*)d_in[2];
    const float* Bm    = (const float*)d_in[3];
    const float* gw    = (const float*)d_in[4];
    float* y = (float*)d_out;

    const size_t HS = (size_t)TOK * H;
    const int ASM = 2 * AP_STG;     // 61440
    const int BSM = BP_TOT;         // 55296

    cudaFuncSetAttribute(aproj_kernel, cudaFuncAttributeMaxDynamicSharedMemorySize, ASM);
    cudaFuncSetAttribute(bproj_kernel, cudaFuncAttributeMaxDynamicSharedMemorySize, BSM);

    wconv_kernel<<<(int)(2 * NWA / 4 / 256), 256>>>(A, Bm);
    for (int i = 0; i < L; i++) {
        const float* xprev = (i == 0) ? hs : y;
        const float* hx    = hs + (size_t)((i == 0) ? 1 : i) * HS;

        mix_gate_kernel<<<TOK / 8, 256>>>(xprev, hx, gw + (size_t)i * E * H, gates, i);
        plan_kernel<<<1, 32>>>();
        aproj_kernel<<<dim3(NTILES, KSPLIT), 256, ASM>>>(i);
        hreduce_kernel<<<TOK * R / 4 / 256, 256>>>();
        bproj_kernel<<<dim3(NTILES, H / 64), 256, BSM>>>(i, y);
    }
}